// round 1
// baseline (speedup 1.0000x reference)
#include <cuda_runtime.h>
#include <cuda_bf16.h>
#include <math.h>

// Shapes (fixed by the problem)
#define B_   128
#define NJ   10
#define NK   1152
#define NM   16
#define NI   8

// ---------------- scratch (device globals; no allocations) ----------------
__device__ float g_uhat[(size_t)B_ * NK * NJ * NM];   // [b][k][j][m]  94.4 MB
__device__ float g_logits[(size_t)B_ * NK * NJ];      // [b][k][j]
__device__ float g_v[B_ * NJ * NM];                   // [b][j][m]
__device__ float g_spart[(size_t)36 * B_ * NJ * NM];  // [kc][b][j][m]
__device__ float g_s0part[(size_t)9 * B_ * NJ * NM];  // [kc][b][j][m]

// =============== Kernel 1: build u_hat + s0 partials =======================
// grid: (kchunk=9, j=10, btile=16), block: 128 threads (g=tid>>5 m-group, p=tid&31 k-par)
// Each thread: Ws[j,k,m4,:] in regs, loops 8 b's from smem x tile.
__global__ void __launch_bounds__(128) uhat_kernel(const float* __restrict__ x,
                                                   const float* __restrict__ Ws) {
    extern __shared__ float sm[];        // x_s[8][128][12] = 48KB (padded rows)
    const int kb = blockIdx.x * 128;
    const int j  = blockIdx.y;
    const int b0 = blockIdx.z * 8;
    const int tid = threadIdx.x;

    // stage x[b0..b0+7, kb..kb+127, 0:8] into smem, padded row = 12 floats
    for (int f = tid; f < 2048; f += 128) {          // 2048 float4
        int b = f >> 8;                              // /256
        int r = f & 255;
        int k = r >> 1, q = r & 1;
        float4 v4 = *(const float4*)(x + ((size_t)(b0 + b) * NK + kb + k) * NI + q * 4);
        *(float4*)(sm + (b * 128 + k) * 12 + q * 4) = v4;
    }
    __syncthreads();

    const int p = tid & 31, g = tid >> 5;
    float acc[32];
#pragma unroll
    for (int t = 0; t < 32; t++) acc[t] = 0.f;

    for (int ki = 0; ki < 4; ki++) {
        const int kl = ki * 32 + p;
        const int k  = kb + kl;
        const float4* wp = (const float4*)(Ws + (((size_t)j * NK + k) * NM + g * 4) * NI);
        float4 w[8];
#pragma unroll
        for (int t = 0; t < 8; t++) w[t] = wp[t];
#pragma unroll
        for (int b = 0; b < 8; b++) {
            const float* xr = sm + (b * 128 + kl) * 12;
            float4 xa = *(const float4*)xr;
            float4 xb = *(const float4*)(xr + 4);
            float4 u;
            u.x = w[0].x*xa.x + w[0].y*xa.y + w[0].z*xa.z + w[0].w*xa.w
                + w[1].x*xb.x + w[1].y*xb.y + w[1].z*xb.z + w[1].w*xb.w;
            u.y = w[2].x*xa.x + w[2].y*xa.y + w[2].z*xa.z + w[2].w*xa.w
                + w[3].x*xb.x + w[3].y*xb.y + w[3].z*xb.z + w[3].w*xb.w;
            u.z = w[4].x*xa.x + w[4].y*xa.y + w[4].z*xa.z + w[4].w*xa.w
                + w[5].x*xb.x + w[5].y*xb.y + w[5].z*xb.z + w[5].w*xb.w;
            u.w = w[6].x*xa.x + w[6].y*xa.y + w[6].z*xa.z + w[6].w*xa.w
                + w[7].x*xb.x + w[7].y*xb.y + w[7].z*xb.z + w[7].w*xb.w;
            *(float4*)(g_uhat + (((size_t)(b0 + b) * NK + k) * (NJ * NM)) + j * NM + g * 4) = u;
            acc[b * 4 + 0] += u.x;
            acc[b * 4 + 1] += u.y;
            acc[b * 4 + 2] += u.z;
            acc[b * 4 + 3] += u.w;
        }
    }
    __syncthreads();
    // in-block reduction over k_par (32) for s0; buf row stride 129 -> conflict-free
    float* buf = sm;                                  // reuse (32*129 floats = 16.5KB)
#pragma unroll
    for (int b = 0; b < 8; b++)
#pragma unroll
        for (int t = 0; t < 4; t++)
            buf[p * 129 + b * 16 + g * 4 + t] = acc[b * 4 + t];
    __syncthreads();
    if (tid < 128) {
        float s = 0.f;
#pragma unroll
        for (int pp = 0; pp < 32; pp++) s += buf[pp * 129 + tid];
        int bloc = tid >> 4, m = tid & 15;
        g_s0part[(((size_t)blockIdx.x * B_ + (b0 + bloc)) * NJ + j) * NM + m] = s;
    }
}

// =============== Kernel 2: fused routing pass ==============================
// ITER==0: logits = delta(v0), store logits, c=softmax -> s partials
// ITER==1: logits = old + delta(v1), c=softmax -> s partials
// grid: (kchunk=36, btile=32), block 160 threads.
template <int ITER>
__global__ void __launch_bounds__(160) route_kernel() {
    extern __shared__ float sm[];
    float* uh = sm;                       // [128 pairs][164]  (row pad)
    float* cs = sm + 128 * 164;           // [128][10]
    float* vs = cs + 1280;                // [4][160]
    const int kb = blockIdx.x * 32;
    const int b0 = blockIdx.y * 4;
    const int tid = threadIdx.x;

    for (int f = tid; f < 640; f += 160) vs[f] = g_v[b0 * (NJ * NM) + f];

    // cooperative coalesced load of the u_hat tile (4b x 32k x 160)
#pragma unroll 4
    for (int it = 0; it < 32; it++) {
        int f = it * 160 + tid;          // 0..5119 float4s
        int pair = f / 40, q = f % 40;
        int bl = pair >> 5, kl = pair & 31;
        float4 u = *(const float4*)(g_uhat + (((size_t)(b0 + bl) * NK + kb + kl) * (NJ * NM)) + q * 4);
        *(float4*)(uh + pair * 164 + q * 4) = u;
    }
    __syncthreads();

    if (tid < 128) {
        const int bl = tid >> 5, kl = tid & 31;
        const float* row  = uh + tid * 164;
        const float* vrow = vs + bl * (NJ * NM);
        float L[10];
#pragma unroll
        for (int j = 0; j < 10; j++) {
            float d = 0.f;
#pragma unroll
            for (int q = 0; q < 4; q++) {
                float4 u  = *(const float4*)(row  + j * NM + q * 4);
                float4 vv = *(const float4*)(vrow + j * NM + q * 4);
                d += u.x * vv.x + u.y * vv.y + u.z * vv.z + u.w * vv.w;
            }
            L[j] = d;
        }
        const size_t gi = ((size_t)(b0 + bl) * NK + kb + kl) * NJ;
        if (ITER > 0) {
#pragma unroll
            for (int j = 0; j < 10; j++) L[j] += g_logits[gi + j];
        } else {
#pragma unroll
            for (int j = 0; j < 10; j++) g_logits[gi + j] = L[j];
        }
        float mx = L[0];
#pragma unroll
        for (int j = 1; j < 10; j++) mx = fmaxf(mx, L[j]);
        float e[10], ssum = 0.f;
#pragma unroll
        for (int j = 0; j < 10; j++) { e[j] = __expf(L[j] - mx); ssum += e[j]; }
        const float inv = 1.f / ssum;
#pragma unroll
        for (int j = 0; j < 10; j++) cs[tid * 10 + j] = e[j] * inv;
    }
    __syncthreads();

    // Phase B: s[b,j,m] partials over this k-chunk (fully in-block, no atomics)
    const int bl = tid / 40, rj = tid % 40, j = rj >> 2, g = rj & 3;
    float4 acc = make_float4(0.f, 0.f, 0.f, 0.f);
    const float* uhb = uh + (bl * 32) * 164 + j * NM + g * 4;
    const float* csb = cs + (bl * 32) * 10 + j;
#pragma unroll
    for (int kl = 0; kl < 32; kl++) {
        float c = csb[kl * 10];
        float4 u = *(const float4*)(uhb + kl * 164);
        acc.x += c * u.x; acc.y += c * u.y; acc.z += c * u.z; acc.w += c * u.w;
    }
    *(float4*)(g_spart + ((((size_t)blockIdx.x * B_) + (b0 + bl)) * NJ + j) * NM + g * 4) = acc;
}

// =============== Kernel 3: reduce partials + squash ========================
template <int P, bool FINAL>
__global__ void squash_kernel(float scale, float* __restrict__ out) {
    const int pair = blockIdx.x * blockDim.x + threadIdx.x;   // b*10+j, 1280 total
    if (pair >= B_ * NJ) return;
    const float* part = (P == 9) ? g_s0part : g_spart;
    float4 s[4];
#pragma unroll
    for (int q = 0; q < 4; q++) s[q] = make_float4(0.f, 0.f, 0.f, 0.f);
    for (int p = 0; p < P; p++) {
        const float4* src = (const float4*)(part + ((size_t)p * (B_ * NJ) + pair) * NM);
#pragma unroll
        for (int q = 0; q < 4; q++) {
            float4 u = src[q];
            s[q].x += u.x; s[q].y += u.y; s[q].z += u.z; s[q].w += u.w;
        }
    }
    float n2 = 0.f;
#pragma unroll
    for (int q = 0; q < 4; q++) {
        s[q].x *= scale; s[q].y *= scale; s[q].z *= scale; s[q].w *= scale;
        n2 += s[q].x * s[q].x + s[q].y * s[q].y + s[q].z * s[q].z + s[q].w * s[q].w;
    }
    const float f = sqrtf(n2) / (1.f + n2);
    float* dst = FINAL ? (out + pair * NM) : (g_v + pair * NM);
#pragma unroll
    for (int q = 0; q < 4; q++) {
        float4 o = make_float4(s[q].x * f, s[q].y * f, s[q].z * f, s[q].w * f);
        *(float4*)(dst + q * 4) = o;
    }
}

// ---------------------------------------------------------------------------
extern "C" void kernel_launch(void* const* d_in, const int* in_sizes, int n_in,
                              void* d_out, int out_size) {
    const float* x  = (const float*)d_in[0];
    const float* Ws = (const float*)d_in[1];
    // defensive: identify by element count (x=1179648, Ws=1474560)
    if (n_in >= 2 && in_sizes[0] == 10 * NK * NM * NI) { const float* t = x; x = Ws; Ws = t; }
    float* out = (float*)d_out;

    const int SMEM_U = 8 * 128 * 12 * 4;                         // 48 KB
    const int SMEM_R = (128 * 164 + 128 * 10 + 4 * 160) * 4;     // 91,648 B
    cudaFuncSetAttribute(route_kernel<0>, cudaFuncAttributeMaxDynamicSharedMemorySize, SMEM_R);
    cudaFuncSetAttribute(route_kernel<1>, cudaFuncAttributeMaxDynamicSharedMemorySize, SMEM_R);

    // 1) u_hat + s0 partials
    uhat_kernel<<<dim3(9, 10, 16), 128, SMEM_U>>>(x, Ws);
    // 2) v0 = squash(0.1 * sum_k u_hat)
    squash_kernel<9, false><<<10, 128>>>(0.1f, out);
    // 3) iter0: b1 = u.v0 (store), c1=softmax(b1), s1 partials
    route_kernel<0><<<dim3(36, 32), 160, SMEM_R>>>();
    // 4) v1 = squash(s1)
    squash_kernel<36, false><<<10, 128>>>(1.f, out);
    // 5) iter1: b2 = b1 + u.v1, c2=softmax(b2), s2 partials
    route_kernel<1><<<dim3(36, 32), 160, SMEM_R>>>();
    // 6) v2 = squash(s2) -> d_out
    squash_kernel<36, true><<<10, 128>>>(1.f, out);
}

// round 2
// speedup vs baseline: 2.4268x; 2.4268x over previous
#include <cuda_runtime.h>
#include <cuda_fp16.h>
#include <math.h>

#define B_   128
#define NJ   10
#define NK   1152
#define NM   16
#define NI   8

// ---------------- scratch (device globals; no allocations) ----------------
// u_hat stored fp16, layout [j][b][k][m]  (47.2 MB)
__device__ __half  g_uhat[(size_t)NJ * B_ * NK * NM];
__device__ float   g_logits[(size_t)B_ * NK * NJ];      // [b][k][j]
__device__ float   g_v[B_ * NJ * NM];                   // [b][j][m]
__device__ float   g_spart[(size_t)36 * B_ * NJ * NM];  // [kc][b][j][m]
__device__ float   g_s0part[(size_t)9 * B_ * NJ * NM];  // [kc][b][j][m]

// =============== Kernel 1: build u_hat (fp16, coalesced) + s0 partials =====
// grid: (kchunk=9, j=10, btile=16), block 128 (g=tid>>5 m-quad, p=tid&31 k-par)
__global__ void __launch_bounds__(128) uhat_kernel(const float* __restrict__ x,
                                                   const float* __restrict__ Ws) {
    extern __shared__ float sm[];
    // layout: x tile [8][128][12] floats (49,152B), then su tile [8*128][10] half2 (40,960B)
    __half2* su = (__half2*)(sm + 8 * 128 * 12);
    const int kb = blockIdx.x * 128;
    const int j  = blockIdx.y;
    const int b0 = blockIdx.z * 8;
    const int tid = threadIdx.x;

    // stage x[b0..b0+7, kb..kb+127, 0:8], padded row = 12 floats
    for (int f = tid; f < 2048; f += 128) {
        int b = f >> 8, r = f & 255;
        int k = r >> 1, q = r & 1;
        float4 v4 = *(const float4*)(x + ((size_t)(b0 + b) * NK + kb + k) * NI + q * 4);
        *(float4*)(sm + (b * 128 + k) * 12 + q * 4) = v4;
    }
    __syncthreads();

    const int p = tid & 31, g = tid >> 5;
    float acc[32];
#pragma unroll
    for (int t = 0; t < 32; t++) acc[t] = 0.f;

    for (int ki = 0; ki < 4; ki++) {
        const int kl = ki * 32 + p;
        const int k  = kb + kl;
        const float4* wp = (const float4*)(Ws + (((size_t)j * NK + k) * NM + g * 4) * NI);
        float4 w[8];
#pragma unroll
        for (int t = 0; t < 8; t++) w[t] = wp[t];
#pragma unroll
        for (int b = 0; b < 8; b++) {
            const float* xr = sm + (b * 128 + kl) * 12;
            float4 xa = *(const float4*)xr;
            float4 xb = *(const float4*)(xr + 4);
            float4 u;
            u.x = w[0].x*xa.x + w[0].y*xa.y + w[0].z*xa.z + w[0].w*xa.w
                + w[1].x*xb.x + w[1].y*xb.y + w[1].z*xb.z + w[1].w*xb.w;
            u.y = w[2].x*xa.x + w[2].y*xa.y + w[2].z*xa.z + w[2].w*xa.w
                + w[3].x*xb.x + w[3].y*xb.y + w[3].z*xb.z + w[3].w*xb.w;
            u.z = w[4].x*xa.x + w[4].y*xa.y + w[4].z*xa.z + w[4].w*xa.w
                + w[5].x*xb.x + w[5].y*xb.y + w[5].z*xb.z + w[5].w*xb.w;
            u.w = w[6].x*xa.x + w[6].y*xa.y + w[6].z*xa.z + w[6].w*xa.w
                + w[7].x*xb.x + w[7].y*xb.y + w[7].z*xb.z + w[7].w*xb.w;
            // stash fp16 into smem tile (row stride 10 half2, 2-way conflict max)
            su[(b * 128 + kl) * 10 + g * 2]     = __float22half2_rn(make_float2(u.x, u.y));
            su[(b * 128 + kl) * 10 + g * 2 + 1] = __float22half2_rn(make_float2(u.z, u.w));
            acc[b * 4 + 0] += u.x;
            acc[b * 4 + 1] += u.y;
            acc[b * 4 + 2] += u.z;
            acc[b * 4 + 3] += u.w;
        }
    }
    __syncthreads();

    // cooperative coalesced fp16 store: per (b,k) 32B contiguous, [j][b][k][m]
    for (int f = tid; f < 2048; f += 128) {    // 2048 uint4 = 8b*128k*2
        int b = f >> 8, r = f & 255;
        int kl = r >> 1, q2 = r & 1;
        const uint2* s2 = (const uint2*)(su + (b * 128 + kl) * 10 + q2 * 4);
        uint4 o; o.x = s2[0].x; o.y = s2[0].y; o.z = s2[1].x; o.w = s2[1].y;
        *(uint4*)(g_uhat + (((size_t)j * B_ + b0 + b) * NK + kb + kl) * NM + q2 * 8) = o;
    }

    // in-block k-reduction (fp32) for s0 partials; reuse x region
    float* buf = sm;
#pragma unroll
    for (int b = 0; b < 8; b++)
#pragma unroll
        for (int t = 0; t < 4; t++)
            buf[p * 129 + b * 16 + g * 4 + t] = acc[b * 4 + t];
    __syncthreads();
    if (tid < 128) {
        float s = 0.f;
#pragma unroll
        for (int pp = 0; pp < 32; pp++) s += buf[pp * 129 + tid];
        int bloc = tid >> 4, m = tid & 15;
        g_s0part[(((size_t)blockIdx.x * B_ + (b0 + bloc)) * NJ + j) * NM + m] = s;
    }
}

// =============== Kernel 2: fused routing pass (fp16 u_hat) =================
// grid: (kchunk=36, btile=32), block 320.  Tile: 4 b x 32 k x 10 j x 16 m.
template <int ITER>
__global__ void __launch_bounds__(320) route_kernel() {
    extern __shared__ float sm[];
    __half2* uh = (__half2*)sm;            // [128 pairs][82 half2]  (80 data + 2 pad)
    float* cs = sm + 128 * 82;             // [128][10]
    float* vs = cs + 1280;                 // [4][160]
    const int kb = blockIdx.x * 32;
    const int b0 = blockIdx.y * 4;
    const int tid = threadIdx.x;

    for (int f = tid; f < 640; f += 320) vs[f] = g_v[b0 * (NJ * NM) + f];

    // cooperative load: [j][b][k][m] fp16, 1KB contiguous per (j,b)
#pragma unroll
    for (int it = 0; it < 8; it++) {
        int f = it * 320 + tid;            // 0..2559 uint4
        int q2 = f & 1, kl = (f >> 1) & 31, bl = (f >> 6) & 3, j = f >> 8;
        uint4 u = *(const uint4*)(g_uhat + (((size_t)j * B_ + b0 + bl) * NK + kb + kl) * NM + q2 * 8);
        __half2* dst = uh + (bl * 32 + kl) * 82 + j * 8 + q2 * 4;
        *(uint2*)dst       = make_uint2(u.x, u.y);
        *(uint2*)(dst + 2) = make_uint2(u.z, u.w);
    }
    __syncthreads();

    if (tid < 128) {                        // one thread per (b,k)
        const int bl = tid >> 5;
        const __half2* row = uh + tid * 82;
        const float* vrow = vs + bl * (NJ * NM);
        float L[10];
#pragma unroll
        for (int j = 0; j < 10; j++) {
            float d = 0.f;
#pragma unroll
            for (int q = 0; q < 8; q++) {
                float2 f2 = __half22float2(row[j * 8 + q]);
                d += f2.x * vrow[j * 16 + q * 2] + f2.y * vrow[j * 16 + q * 2 + 1];
            }
            L[j] = d;
        }
        const size_t gi = ((size_t)(b0 + bl) * NK + kb + (tid & 31)) * NJ;
        if (ITER > 0) {
#pragma unroll
            for (int j = 0; j < 10; j++) L[j] += g_logits[gi + j];
        } else {
#pragma unroll
            for (int j = 0; j < 10; j++) g_logits[gi + j] = L[j];
        }
        float mx = L[0];
#pragma unroll
        for (int j = 1; j < 10; j++) mx = fmaxf(mx, L[j]);
        float e[10], ssum = 0.f;
#pragma unroll
        for (int j = 0; j < 10; j++) { e[j] = __expf(L[j] - mx); ssum += e[j]; }
        const float inv = 1.f / ssum;
#pragma unroll
        for (int j = 0; j < 10; j++) cs[tid * 10 + j] = e[j] * inv;
    }
    __syncthreads();

    // Phase B: s partials. thread = (bl, j, m-half2): 4*10*8 = 320
    const int bl = tid / 80, r = tid % 80, j = r >> 3, mh = r & 7;
    float2 acc = make_float2(0.f, 0.f);
    const __half2* uhb = uh + (bl * 32) * 82 + j * 8 + mh;
    const float* csb = cs + (bl * 32) * 10 + j;
#pragma unroll
    for (int kl = 0; kl < 32; kl++) {
        float c = csb[kl * 10];
        float2 f2 = __half22float2(uhb[kl * 82]);
        acc.x += c * f2.x; acc.y += c * f2.y;
    }
    *(float2*)(g_spart + ((((size_t)blockIdx.x * B_) + (b0 + bl)) * NJ + j) * NM + mh * 2) = acc;
}

// =============== Kernel 3: reduce partials + squash (warp per pair) ========
template <int P, bool FINAL>
__global__ void squash_kernel(float scale, float* __restrict__ out) {
    const int warp = (blockIdx.x * blockDim.x + threadIdx.x) >> 5;
    const int lane = threadIdx.x & 31;
    if (warp >= B_ * NJ) return;
    const float* part = (P == 9) ? g_s0part : g_spart;
    const int q = lane >> 3, t = lane & 7;
    float4 s = make_float4(0.f, 0.f, 0.f, 0.f);
    for (int p = t; p < P; p += 8) {
        float4 u = *(const float4*)(part + ((size_t)p * (B_ * NJ) + warp) * NM + q * 4);
        s.x += u.x; s.y += u.y; s.z += u.z; s.w += u.w;
    }
#pragma unroll
    for (int off = 4; off; off >>= 1) {
        s.x += __shfl_down_sync(0xFFFFFFFFu, s.x, off);
        s.y += __shfl_down_sync(0xFFFFFFFFu, s.y, off);
        s.z += __shfl_down_sync(0xFFFFFFFFu, s.z, off);
        s.w += __shfl_down_sync(0xFFFFFFFFu, s.w, off);
    }
    s.x *= scale; s.y *= scale; s.z *= scale; s.w *= scale;
    float n2 = s.x * s.x + s.y * s.y + s.z * s.z + s.w * s.w;   // valid on t==0
    float n2tot = 0.f;
#pragma unroll
    for (int qq = 0; qq < 4; qq++) n2tot += __shfl_sync(0xFFFFFFFFu, n2, qq * 8);
    const float f = sqrtf(n2tot) / (1.f + n2tot);
    if (t == 0) {
        float* dst = (FINAL ? out : g_v) + warp * NM + q * 4;
        *(float4*)dst = make_float4(s.x * f, s.y * f, s.z * f, s.w * f);
    }
}

// ---------------------------------------------------------------------------
extern "C" void kernel_launch(void* const* d_in, const int* in_sizes, int n_in,
                              void* d_out, int out_size) {
    const float* x  = (const float*)d_in[0];
    const float* Ws = (const float*)d_in[1];
    if (n_in >= 2 && in_sizes[0] == NJ * NK * NM * NI) { const float* t = x; x = Ws; Ws = t; }
    float* out = (float*)d_out;

    const int SMEM_U = 8 * 128 * 12 * 4 + 8 * 128 * 10 * 4;          // 49,152 + 40,960 = 90,112 B
    const int SMEM_R = (128 * 82 + 1280 + 640) * 4;                  // 49,664 B
    cudaFuncSetAttribute(uhat_kernel,     cudaFuncAttributeMaxDynamicSharedMemorySize, SMEM_U);
    cudaFuncSetAttribute(route_kernel<0>, cudaFuncAttributeMaxDynamicSharedMemorySize, SMEM_R);
    cudaFuncSetAttribute(route_kernel<1>, cudaFuncAttributeMaxDynamicSharedMemorySize, SMEM_R);

    // 1) u_hat (fp16, [j][b][k][m]) + s0 partials
    uhat_kernel<<<dim3(9, 10, 16), 128, SMEM_U>>>(x, Ws);
    // 2) v0 = squash(0.1 * sum_k u_hat)
    squash_kernel<9,  false><<<160, 256>>>(0.1f, out);
    // 3) iter0: b1 = u.v0 (store), c1 = softmax(b1), s1 partials
    route_kernel<0><<<dim3(36, 32), 320, SMEM_R>>>();
    // 4) v1 = squash(s1)
    squash_kernel<36, false><<<160, 256>>>(1.f, out);
    // 5) iter1: b2 = b1 + u.v1, c2 = softmax(b2), s2 partials
    route_kernel<1><<<dim3(36, 32), 320, SMEM_R>>>();
    // 6) v2 = squash(s2) -> d_out
    squash_kernel<36, true><<<160, 256>>>(1.f, out);
}